// round 9
// baseline (speedup 1.0000x reference)
#include <cuda_runtime.h>
#include <cstdint>

// Problem constants (fixed by the dataset)
#define N_ELEMS          26214400
#define N_GRIDS          1048576
#define TPB              512
#define GRIDS_PER_CHUNK  256                        // 2 threads per grid
#define ELEMS_PER_CHUNK  (GRIDS_PER_CHUNK * 25)     // 6400 floats
#define VEC_PER_CHUNK    (ELEMS_PER_CHUNK / 4)      // 1600 float4
#define N_CHUNKS         (N_GRIDS / GRIDS_PER_CHUNK)   // 4096
#define ARR_BYTES        (ELEMS_PER_CHUNK * 4)      // 25600 per array
#define STAGE_BYTES      (2 * ARR_BYTES)            // 51200 (preds + targets)
#define NSTAGES          2
#define N_CTAS           296                        // 2 persistent CTAs per SM
#define FIX_SCALE        1048576.0                  // 2^20 fixed point for loss1

// smem: [stage0 | stage1 | mbar0 mbar1]; stage = [preds 25600 | targets 25600]
#define SMEM_MBAR        (NSTAGES * STAGE_BYTES)    // 102400
#define SMEM_TOTAL       (SMEM_MBAR + NSTAGES * 8 + 16)

// Deterministic accumulators (zero at load; last CTA of every launch resets
// them, so the invariant holds across the correctness run and every replay).
__device__ unsigned long long g_sum  = 0;
__device__ int                g_dup  = 0;
__device__ int                g_oob  = 0;
__device__ unsigned int       g_done = 0;

__device__ __forceinline__ uint32_t smem_u32(const void* p) {
    uint32_t a;
    asm("{ .reg .u64 t; cvta.to.shared.u64 t, %1; cvt.u32.u64 %0, t; }"
        : "=r"(a) : "l"(p));
    return a;
}

__device__ __forceinline__ void issue_chunk(uint32_t sbase, int stage,
                                            const float* preds, const int* targets,
                                            long chunk) {
    const uint32_t dstp = sbase + stage * STAGE_BYTES;
    const uint32_t dstt = dstp + ARR_BYTES;
    const uint32_t mbar = sbase + SMEM_MBAR + stage * 8;
    const long base = chunk * ELEMS_PER_CHUNK;
    asm volatile("mbarrier.arrive.expect_tx.shared.b64 _, [%0], %1;"
                 :: "r"(mbar), "r"((uint32_t)STAGE_BYTES) : "memory");
    asm volatile(
        "cp.async.bulk.shared::cta.global.mbarrier::complete_tx::bytes "
        "[%0], [%1], %2, [%3];"
        :: "r"(dstp), "l"(preds + base), "r"((uint32_t)ARR_BYTES), "r"(mbar)
        : "memory");
    asm volatile(
        "cp.async.bulk.shared::cta.global.mbarrier::complete_tx::bytes "
        "[%0], [%1], %2, [%3];"
        :: "r"(dstt), "l"(targets + base), "r"((uint32_t)ARR_BYTES), "r"(mbar)
        : "memory");
}

__device__ __forceinline__ void wait_full(uint32_t sbase, int stage, uint32_t parity) {
    const uint32_t mbar = sbase + SMEM_MBAR + stage * 8;
    uint32_t done;
    asm volatile(
        "{\n\t.reg .pred p;\n\t"
        "mbarrier.try_wait.parity.acquire.cta.shared::cta.b64 p, [%1], %2;\n\t"
        "selp.b32 %0, 1, 0, p;\n\t}"
        : "=r"(done) : "r"(mbar), "r"(parity) : "memory");
    while (!done) {
        asm volatile(
            "{\n\t.reg .pred p;\n\t"
            "mbarrier.try_wait.parity.acquire.cta.shared::cta.b64 p, [%1], %2, 0x989680;\n\t"
            "selp.b32 %0, 1, 0, p;\n\t}"
            : "=r"(done) : "r"(mbar), "r"(parity) : "memory");
    }
}

__global__ __launch_bounds__(TPB) void fused_loss(
    const float* __restrict__ preds,
    const int*   __restrict__ targets,
    float*       __restrict__ out)
{
    extern __shared__ char smem[];
    const uint32_t sbase = smem_u32(smem);
    const int tid = threadIdx.x;
    const int bid = blockIdx.x;

    // chunks handled by this CTA: bid, bid+296, ... (< N_CHUNKS)
    const int nchunks = (N_CHUNKS - bid + N_CTAS - 1) / N_CTAS;

    if (tid == 0) {
        asm volatile("mbarrier.init.shared.b64 [%0], 1;"
                     :: "r"(sbase + SMEM_MBAR + 0) : "memory");
        asm volatile("mbarrier.init.shared.b64 [%0], 1;"
                     :: "r"(sbase + SMEM_MBAR + 8) : "memory");
    }
    __syncthreads();

    // Prologue: fill both stages
    if (tid == 0) {
        if (nchunks > 0) issue_chunk(sbase, 0, preds, targets, (long)bid);
        if (nchunks > 1) issue_chunk(sbase, 1, preds, targets, (long)bid + N_CTAS);
    }

    float acc = 0.0f;
    float mn  =  1e30f;
    float mx  = -1e30f;
    int   dup = 0;

    const int my_grid = tid >> 1;       // grid owned by this thread pair
    const int do_cols = tid & 1;        // even thread: rows; odd thread: cols

    for (int k = 0; k < nchunks; k++) {
        const int      s      = k & 1;
        const uint32_t parity = (k >> 1) & 1;
        wait_full(sbase, s, parity);

        const char*   stg = smem + s * STAGE_BYTES;
        const float4* sp4 = (const float4*)stg;
        const int4*   st4 = (const int4*)(stg + ARR_BYTES);
        const float*  sp  = (const float*)stg;

        // loss1 + oob: both arrays from smem (LDS.128, conflict-free)
        #pragma unroll
        for (int j = 0; j < 4; j++) {
            const int i = tid + j * TPB;
            if (i < VEC_PER_CHUNK) {
                const float4 pp = sp4[i];
                const int4   tt = st4[i];
                acc += fabsf(pp.x - (float)tt.x);
                acc += fabsf(pp.y - (float)tt.y);
                acc += fabsf(pp.z - (float)tt.z);
                acc += fabsf(pp.w - (float)tt.w);
                mn = fminf(mn, fminf(fminf(pp.x, pp.y), fminf(pp.z, pp.w)));
                mx = fmaxf(mx, fmaxf(fmaxf(pp.x, pp.y), fmaxf(pp.z, pp.w)));
            }
        }

        // Duplicate counting: thread pair (2g, 2g+1) owns grid g; even thread
        // checks rows, odd checks cols. Pair lanes read identical addresses
        // (smem broadcast); across the warp 16 distinct words, stride 25 is
        // coprime with 32 banks -> conflict-free.
        float a[25];
        #pragma unroll
        for (int i = 0; i < 25; i++) a[i] = sp[my_grid * 25 + i];

        if (do_cols) {
            #pragma unroll
            for (int c = 0; c < 5; c++) {
                #pragma unroll
                for (int j = 1; j < 5; j++) {
                    bool d = false;
                    #pragma unroll
                    for (int kk = 0; kk < j; kk++) d |= (a[5 * j + c] == a[5 * kk + c]);
                    dup += d;
                }
            }
        } else {
            #pragma unroll
            for (int r = 0; r < 5; r++) {
                #pragma unroll
                for (int j = 1; j < 5; j++) {
                    bool d = false;
                    #pragma unroll
                    for (int kk = 0; kk < j; kk++) d |= (a[5 * r + j] == a[5 * r + kk]);
                    dup += d;
                }
            }
        }

        // All threads done with stage s -> safe to overwrite
        __syncthreads();
        if (tid == 0 && k + NSTAGES < nchunks)
            issue_chunk(sbase, s, preds, targets,
                        (long)bid + (long)(k + NSTAGES) * N_CTAS);
    }

    int oob = (mn < 0.5f) | (mx > 5.5f);

    // ---- Final block reduction (once per CTA) ----
    #pragma unroll
    for (int off = 16; off > 0; off >>= 1) {
        acc += __shfl_down_sync(0xffffffff, acc, off);
        dup += __shfl_down_sync(0xffffffff, dup, off);
        oob |= __shfl_down_sync(0xffffffff, oob, off);
    }
    __shared__ float wabs[16];
    __shared__ int   wdup[16];
    __shared__ int   woob[16];
    __shared__ bool  is_last;
    if ((tid & 31) == 0) {
        wabs[tid >> 5] = acc;
        wdup[tid >> 5] = dup;
        woob[tid >> 5] = oob;
    }
    __syncthreads();

    if (tid == 0) {
        float ba = 0.0f; int bd = 0, bo = 0;
        #pragma unroll
        for (int w = 0; w < 16; w++) { ba += wabs[w]; bd += wdup[w]; bo |= woob[w]; }

        // Deterministic accumulation: fixed-point integer atomics only.
        unsigned long long q = (unsigned long long)llrint((double)ba * FIX_SCALE);
        atomicAdd(&g_sum, q);
        atomicAdd(&g_dup, bd);
        if (bo) atomicOr(&g_oob, 1);
        __threadfence();
        unsigned int prev = atomicAdd(&g_done, 1u);
        is_last = (prev == (unsigned int)(gridDim.x - 1));
    }
    __syncthreads();

    // ---- Last CTA finalizes and self-resets globals for the next replay ----
    if (is_last && tid == 0) {
        unsigned long long s = atomicAdd(&g_sum, 0ULL);
        int td = atomicAdd(&g_dup, 0);
        int to = atomicOr(&g_oob, 0);

        double loss1 = (double)s / (FIX_SCALE * (double)N_ELEMS);
        double loss2 = ((double)td / (double)N_GRIDS) * 0.1;
        out[0] = (float)(loss1 + loss2 + (to ? 1000.0 : 0.0));

        g_sum  = 0ULL;
        g_dup  = 0;
        g_oob  = 0;
        __threadfence();
        g_done = 0;
    }
}

extern "C" void kernel_launch(void* const* d_in, const int* in_sizes, int n_in,
                              void* d_out, int out_size) {
    const float* preds   = (const float*)d_in[0];
    const int*   targets = (const int*)d_in[1];
    float*       out     = (float*)d_out;

    static bool attr_set = false;
    if (!attr_set) {
        cudaFuncSetAttribute(fused_loss,
                             cudaFuncAttributeMaxDynamicSharedMemorySize,
                             SMEM_TOTAL);
        attr_set = true;
    }
    fused_loss<<<N_CTAS, TPB, SMEM_TOTAL>>>(preds, targets, out);
}

// round 13
// speedup vs baseline: 1.1089x; 1.1089x over previous
#include <cuda_runtime.h>
#include <cstdint>

// Problem constants (fixed by the dataset)
#define N_ELEMS          26214400
#define N_GRIDS          1048576
#define TPB              256
#define GRIDS_PER_CHUNK  256                        // one grid per thread
#define ELEMS_PER_CHUNK  (GRIDS_PER_CHUNK * 25)     // 6400 floats
#define VEC_PER_CHUNK    (ELEMS_PER_CHUNK / 4)      // 1600 float4
#define N_CHUNKS         (N_GRIDS / GRIDS_PER_CHUNK)   // 4096
#define ARR_BYTES        (ELEMS_PER_CHUNK * 4)      // 25600 (preds only staged)
#define STAGE_BYTES      ARR_BYTES
#define NSTAGES          2
#define N_CTAS           444                        // 3 persistent CTAs per SM
#define FIX_SCALE        1048576.0                  // 2^20 fixed point for loss1

// smem: [stage0 preds | stage1 preds | mbar0 mbar1]
#define SMEM_MBAR        (NSTAGES * STAGE_BYTES)    // 51200
#define SMEM_TOTAL       (SMEM_MBAR + NSTAGES * 8 + 16)

// Deterministic accumulators (zero at load; last CTA of every launch resets
// them, so the invariant holds across the correctness run and every replay).
__device__ unsigned long long g_sum  = 0;
__device__ int                g_dup  = 0;
__device__ int                g_oob  = 0;
__device__ unsigned int       g_done = 0;

__device__ __forceinline__ uint32_t smem_u32(const void* p) {
    uint32_t a;
    asm("{ .reg .u64 t; cvta.to.shared.u64 t, %1; cvt.u32.u64 %0, t; }"
        : "=r"(a) : "l"(p));
    return a;
}

__device__ __forceinline__ void issue_chunk(uint32_t sbase, int stage,
                                            const float* preds, long chunk) {
    const uint32_t dstp = sbase + stage * STAGE_BYTES;
    const uint32_t mbar = sbase + SMEM_MBAR + stage * 8;
    asm volatile("mbarrier.arrive.expect_tx.shared.b64 _, [%0], %1;"
                 :: "r"(mbar), "r"((uint32_t)STAGE_BYTES) : "memory");
    asm volatile(
        "cp.async.bulk.shared::cta.global.mbarrier::complete_tx::bytes "
        "[%0], [%1], %2, [%3];"
        :: "r"(dstp), "l"(preds + chunk * ELEMS_PER_CHUNK),
           "r"((uint32_t)ARR_BYTES), "r"(mbar)
        : "memory");
}

__device__ __forceinline__ void wait_full(uint32_t sbase, int stage, uint32_t parity) {
    const uint32_t mbar = sbase + SMEM_MBAR + stage * 8;
    uint32_t done;
    asm volatile(
        "{\n\t.reg .pred p;\n\t"
        "mbarrier.try_wait.parity.acquire.cta.shared::cta.b64 p, [%1], %2;\n\t"
        "selp.b32 %0, 1, 0, p;\n\t}"
        : "=r"(done) : "r"(mbar), "r"(parity) : "memory");
    while (!done) {
        asm volatile(
            "{\n\t.reg .pred p;\n\t"
            "mbarrier.try_wait.parity.acquire.cta.shared::cta.b64 p, [%1], %2, 0x989680;\n\t"
            "selp.b32 %0, 1, 0, p;\n\t}"
            : "=r"(done) : "r"(mbar), "r"(parity) : "memory");
    }
}

// min 3 blocks/SM -> ptxas budgets <=85 regs (room for the 7x int4 target
// batch + base ~44 without spilling; do NOT tighten further, see R2).
__global__ __launch_bounds__(TPB, 3) void fused_loss(
    const float* __restrict__ preds,
    const int*   __restrict__ targets,
    float*       __restrict__ out)
{
    extern __shared__ char smem[];
    const uint32_t sbase = smem_u32(smem);
    const int tid = threadIdx.x;
    const int bid = blockIdx.x;

    // chunks handled by this CTA: bid, bid+444, ... (< N_CHUNKS)
    const int nchunks = (N_CHUNKS - bid + N_CTAS - 1) / N_CTAS;

    if (tid == 0) {
        asm volatile("mbarrier.init.shared.b64 [%0], 1;"
                     :: "r"(sbase + SMEM_MBAR + 0) : "memory");
        asm volatile("mbarrier.init.shared.b64 [%0], 1;"
                     :: "r"(sbase + SMEM_MBAR + 8) : "memory");
    }
    __syncthreads();

    // Prologue: fill both preds stages (targets stream via hoisted LDG)
    if (tid == 0) {
        if (nchunks > 0) issue_chunk(sbase, 0, preds, (long)bid);
        if (nchunks > 1) issue_chunk(sbase, 1, preds, (long)bid + N_CTAS);
    }

    float acc = 0.0f;
    float mn  =  1e30f;
    float mx  = -1e30f;
    int   dup = 0;

    for (int k = 0; k < nchunks; k++) {
        const int      s      = k & 1;
        const uint32_t parity = (k >> 1) & 1;
        const long     chunk  = (long)bid + (long)k * N_CTAS;
        const int4* __restrict__ t4 =
            (const int4*)(targets + chunk * ELEMS_PER_CHUNK);

        // ---- Hoist ALL target loads above the wait: their ~600cyc DRAM
        //      latency is absorbed by the mbarrier sleep below. ----
        int4 tt[7];
        #pragma unroll
        for (int j = 0; j < 7; j++) {
            const int i = tid + j * TPB;
            if (i < VEC_PER_CHUNK) tt[j] = __ldcs(t4 + i);
        }

        wait_full(sbase, s, parity);

        const char*   stg = smem + s * STAGE_BYTES;
        const float4* sp4 = (const float4*)stg;
        const float*  sp  = (const float*)stg;

        // loss1 + oob: preds from smem (LDS.128), targets from registers
        #pragma unroll
        for (int j = 0; j < 7; j++) {
            const int i = tid + j * TPB;
            if (i < VEC_PER_CHUNK) {
                const float4 pp = sp4[i];
                acc += fabsf(pp.x - (float)tt[j].x);
                acc += fabsf(pp.y - (float)tt[j].y);
                acc += fabsf(pp.z - (float)tt[j].z);
                acc += fabsf(pp.w - (float)tt[j].w);
                mn = fminf(mn, fminf(fminf(pp.x, pp.y), fminf(pp.z, pp.w)));
                mx = fmaxf(mx, fmaxf(fmaxf(pp.x, pp.y), fmaxf(pp.z, pp.w)));
            }
        }

        // Duplicate counting: thread tid owns grid tid of this chunk.
        // Stride 25 is coprime with 32 banks -> conflict-free scalar LDS.
        float a[25];
        #pragma unroll
        for (int i = 0; i < 25; i++) a[i] = sp[tid * 25 + i];

        #pragma unroll
        for (int r = 0; r < 5; r++) {
            #pragma unroll
            for (int j = 1; j < 5; j++) {
                bool d = false;
                #pragma unroll
                for (int kk = 0; kk < j; kk++) d |= (a[5 * r + j] == a[5 * r + kk]);
                dup += d;
            }
        }
        #pragma unroll
        for (int c = 0; c < 5; c++) {
            #pragma unroll
            for (int j = 1; j < 5; j++) {
                bool d = false;
                #pragma unroll
                for (int kk = 0; kk < j; kk++) d |= (a[5 * j + c] == a[5 * kk + c]);
                dup += d;
            }
        }

        // All threads done with stage s -> safe to overwrite
        __syncthreads();
        if (tid == 0 && k + NSTAGES < nchunks)
            issue_chunk(sbase, s, preds, (long)bid + (long)(k + NSTAGES) * N_CTAS);
    }

    int oob = (mn < 0.5f) | (mx > 5.5f);

    // ---- Final block reduction (once per CTA) ----
    #pragma unroll
    for (int off = 16; off > 0; off >>= 1) {
        acc += __shfl_down_sync(0xffffffff, acc, off);
        dup += __shfl_down_sync(0xffffffff, dup, off);
        oob |= __shfl_down_sync(0xffffffff, oob, off);
    }
    __shared__ float wabs[8];
    __shared__ int   wdup[8];
    __shared__ int   woob[8];
    __shared__ bool  is_last;
    if ((tid & 31) == 0) {
        wabs[tid >> 5] = acc;
        wdup[tid >> 5] = dup;
        woob[tid >> 5] = oob;
    }
    __syncthreads();

    if (tid == 0) {
        float ba = 0.0f; int bd = 0, bo = 0;
        #pragma unroll
        for (int w = 0; w < 8; w++) { ba += wabs[w]; bd += wdup[w]; bo |= woob[w]; }

        // Deterministic accumulation: fixed-point integer atomics only.
        unsigned long long q = (unsigned long long)llrint((double)ba * FIX_SCALE);
        atomicAdd(&g_sum, q);
        atomicAdd(&g_dup, bd);
        if (bo) atomicOr(&g_oob, 1);
        __threadfence();
        unsigned int prev = atomicAdd(&g_done, 1u);
        is_last = (prev == (unsigned int)(gridDim.x - 1));
    }
    __syncthreads();

    // ---- Last CTA finalizes and self-resets globals for the next replay ----
    if (is_last && tid == 0) {
        unsigned long long s = atomicAdd(&g_sum, 0ULL);
        int td = atomicAdd(&g_dup, 0);
        int to = atomicOr(&g_oob, 0);

        double loss1 = (double)s / (FIX_SCALE * (double)N_ELEMS);
        double loss2 = ((double)td / (double)N_GRIDS) * 0.1;
        out[0] = (float)(loss1 + loss2 + (to ? 1000.0 : 0.0));

        g_sum  = 0ULL;
        g_dup  = 0;
        g_oob  = 0;
        __threadfence();
        g_done = 0;
    }
}

extern "C" void kernel_launch(void* const* d_in, const int* in_sizes, int n_in,
                              void* d_out, int out_size) {
    const float* preds   = (const float*)d_in[0];
    const int*   targets = (const int*)d_in[1];
    float*       out     = (float*)d_out;

    static bool attr_set = false;
    if (!attr_set) {
        cudaFuncSetAttribute(fused_loss,
                             cudaFuncAttributeMaxDynamicSharedMemorySize,
                             SMEM_TOTAL);
        attr_set = true;
    }
    fused_loss<<<N_CTAS, TPB, SMEM_TOTAL>>>(preds, targets, out);
}